// round 2
// baseline (speedup 1.0000x reference)
#include <cuda_runtime.h>
#include <cuda_bf16.h>

// Entmax15: out = clip(X - tau*, 0)^2, sum(out) = 1 per row, where
// X = (masked_scores - rowmax) * 0.5.
//
// tau* found by exact piecewise-quadratic iteration (Michelot-style):
// on the current support A = {x > tau}, f(tau') = sum_A (x - tau')^2 is an
// exact quadratic; jump straight to its root each step. Converges in ~3-4
// steps, finite termination when the support size repeats.

constexpr int S_LEN    = 2048;
constexpr int THREADS  = 256;
constexpr int WARPS    = THREADS / 32;
constexpr float NEG_FILL = -1e4f;

__global__ void __launch_bounds__(THREADS, 6)
entmax15_kernel(const float* __restrict__ scores,
                const int*   __restrict__ mask,
                float*       __restrict__ out)
{
    const long long base = (long long)blockIdx.x * S_LEN;
    const float4* s4 = reinterpret_cast<const float4*>(scores + base);
    const int4*   m4 = reinterpret_cast<const int4*>(mask + base);
    float4*       o4 = reinterpret_cast<float4*>(out + base);

    const int tid  = threadIdx.x;
    const int warp = tid >> 5;
    const int lane = tid & 31;

    // ---- load 8 elems/thread (streaming), apply mask ----
    float4 a = __ldcs(s4 + tid);
    float4 b = __ldcs(s4 + tid + THREADS);
    int4  ma = __ldcs(m4 + tid);
    int4  mb = __ldcs(m4 + tid + THREADS);

    float x[8];
    x[0] = ma.x ? a.x : NEG_FILL;
    x[1] = ma.y ? a.y : NEG_FILL;
    x[2] = ma.z ? a.z : NEG_FILL;
    x[3] = ma.w ? a.w : NEG_FILL;
    x[4] = mb.x ? b.x : NEG_FILL;
    x[5] = mb.y ? b.y : NEG_FILL;
    x[6] = mb.z ? b.z : NEG_FILL;
    x[7] = mb.w ? b.w : NEG_FILL;

    __shared__ float  shmax[WARPS];
    __shared__ float4 red[2][WARPS];   // double-buffered (k, S1, S2, -) per warp

    // ---- block max: warp reduce -> smem -> all threads reduce 8 values ----
    float mx = x[0];
    #pragma unroll
    for (int i = 1; i < 8; ++i) mx = fmaxf(mx, x[i]);
    #pragma unroll
    for (int o = 16; o; o >>= 1) mx = fmaxf(mx, __shfl_xor_sync(0xffffffffu, mx, o));
    if (lane == 0) shmax[warp] = mx;
    __syncthreads();
    mx = shmax[0];
    #pragma unroll
    for (int w = 1; w < WARPS; ++w) mx = fmaxf(mx, shmax[w]);

    // ---- alpha=1.5 transform: X = (x - max) * 0.5, so max(X) == 0 ----
    const float mxh = mx * 0.5f;
    #pragma unroll
    for (int i = 0; i < 8; ++i) x[i] = fmaf(x[i], 0.5f, -mxh);

    // ---- exact piecewise-quadratic root find; tau* in [-1, 0) ----
    float tau    = -1.0f;   // max element alone forces tau* >= -1
    float prev_k = -1.0f;
    int   p      = 0;

    #pragma unroll 1
    for (int it = 0; it < 24; ++it) {
        float k = 0.0f, s1 = 0.0f, s2 = 0.0f;
        #pragma unroll
        for (int i = 0; i < 8; ++i) {
            float d  = x[i] - tau;
            float dc = fmaxf(d, 0.0f);
            k  += (d > 0.0f) ? 1.0f : 0.0f;
            s1 += dc;
            s2  = fmaf(dc, dc, s2);
        }
        #pragma unroll
        for (int o = 16; o; o >>= 1) {
            k  += __shfl_xor_sync(0xffffffffu, k,  o);
            s1 += __shfl_xor_sync(0xffffffffu, s1, o);
            s2 += __shfl_xor_sync(0xffffffffu, s2, o);
        }
        if (lane == 0) red[p][warp] = make_float4(k, s1, s2, 0.0f);
        __syncthreads();

        float K = 0.0f, S1 = 0.0f, S2 = 0.0f;
        #pragma unroll
        for (int w = 0; w < WARPS; ++w) {
            float4 r = red[p][w];
            K += r.x; S1 += r.y; S2 += r.z;
        }
        p ^= 1;

        if (K == prev_k) break;          // same support twice -> tau exact
        prev_k = K;

        // solve K*delta^2 - 2*S1*delta + (S2 - 1) = 0, smaller root
        float disc = fmaxf(fmaf(-K, S2 - 1.0f, S1 * S1), 0.0f);
        tau += (S1 - sqrtf(disc)) / K;
    }

    // ---- emit p = clip(X - tau, 0)^2 (streaming stores) ----
    float4 r0, r1;
    float d;
    d = fmaxf(x[0] - tau, 0.0f); r0.x = d * d;
    d = fmaxf(x[1] - tau, 0.0f); r0.y = d * d;
    d = fmaxf(x[2] - tau, 0.0f); r0.z = d * d;
    d = fmaxf(x[3] - tau, 0.0f); r0.w = d * d;
    d = fmaxf(x[4] - tau, 0.0f); r1.x = d * d;
    d = fmaxf(x[5] - tau, 0.0f); r1.y = d * d;
    d = fmaxf(x[6] - tau, 0.0f); r1.z = d * d;
    d = fmaxf(x[7] - tau, 0.0f); r1.w = d * d;
    __stcs(o4 + tid,           r0);
    __stcs(o4 + tid + THREADS, r1);
}

extern "C" void kernel_launch(void* const* d_in, const int* in_sizes, int n_in,
                              void* d_out, int out_size)
{
    const float* scores = (const float*)d_in[0];
    const int*   mask   = (const int*)d_in[1];
    float*       out    = (float*)d_out;
    const int rows = in_sizes[0] / S_LEN;
    entmax15_kernel<<<rows, THREADS>>>(scores, mask, out);
}